// round 14
// baseline (speedup 1.0000x reference)
#include <cuda_runtime.h>
#include <cuda_bf16.h>
#include <stdint.h>
#include <cstdint>
#include <math.h>

// Problem constants
#define SQ   2048
#define DM   1024
#define NH   16
#define DH   64
#define BT   2
#define NTOK (BT*SQ)      // 4096
#define DMLP 4096

typedef __nv_bfloat16 bf16;

// ---------------- scratch (device globals; no allocations allowed) ----------
__device__ float g_q   [NTOK*DM];      // [B,H,S,DH] fp32
__device__ float g_k   [NTOK*DM];
__device__ float g_v   [NTOK*DM];
__device__ float g_rmid[NTOK*DM];
__device__ float g_z   [NTOK*DM];      // attn out fp32 [tok, h*64+dh]
__device__ float g_actf[NTOK*DMLP];    // relu acts fp32

// int8 hi/lo activations + per-row scales
__device__ int8_t g_xa1[NTOK*DM],   g_xa0[NTOK*DM];
__device__ int8_t g_z1 [NTOK*DM],   g_z0 [NTOK*DM];
__device__ int8_t g_h21[NTOK*DM],   g_h20[NTOK*DM];
__device__ int8_t g_ac1[NTOK*DMLP], g_ac0[NTOK*DMLP];
__device__ float  g_sx[NTOK], g_sz[NTOK], g_sh[NTOK], g_sa[NTOK];

// int8 hi/lo weights, TRANSPOSED [N,K] row-major, + per-N absmax bits
__device__ int8_t g_wq1[DM*DM],   g_wq0[DM*DM];
__device__ int8_t g_wk1[DM*DM],   g_wk0[DM*DM];
__device__ int8_t g_wv1[DM*DM],   g_wv0[DM*DM];
__device__ int8_t g_wo1[DM*DM],   g_wo0[DM*DM];
__device__ int8_t g_wi1[DMLP*DM], g_wi0[DMLP*DM];   // W_in^T  [4096,1024]
__device__ int8_t g_wu1[DM*DMLP], g_wu0[DM*DMLP];   // W_out^T [1024,4096]
__device__ unsigned g_bq[DM], g_bk[DM], g_bv[DM], g_bo[DM], g_bi[DMLP], g_bu[DM];

// ---------------- small helpers ----------------------------------------------
__device__ __forceinline__ uint32_t smem_u32(const void* p) {
    return (uint32_t)__cvta_generic_to_shared(p);
}
__device__ __forceinline__ void cp16(uint32_t dst, const void* src) {
    asm volatile("cp.async.cg.shared.global [%0], [%1], 16;"
                 :: "r"(dst), "l"((unsigned long long)__cvta_generic_to_global(src)));
}
#define CP_COMMIT() asm volatile("cp.async.commit_group;")
#define CP_WAIT1()  asm volatile("cp.async.wait_group 1;")
#define CP_WAIT0()  asm volatile("cp.async.wait_group 0;")

#define LDSM_X4(r0,r1,r2,r3,addr) \
    asm volatile("ldmatrix.sync.aligned.m8n8.x4.shared.b16 {%0,%1,%2,%3}, [%4];" \
        : "=r"(r0),"=r"(r1),"=r"(r2),"=r"(r3) : "r"(addr))
#define LDSM_X4_T(r0,r1,r2,r3,addr) \
    asm volatile("ldmatrix.sync.aligned.m8n8.x4.trans.shared.b16 {%0,%1,%2,%3}, [%4];" \
        : "=r"(r0),"=r"(r1),"=r"(r2),"=r"(r3) : "r"(addr))
#define MMA16816(c, a0,a1,a2,a3, b0,b1) \
    asm volatile("mma.sync.aligned.m16n8k16.row.col.f32.bf16.bf16.f32 " \
        "{%0,%1,%2,%3}, {%4,%5,%6,%7}, {%8,%9}, {%0,%1,%2,%3};" \
        : "+f"(c[0]),"+f"(c[1]),"+f"(c[2]),"+f"(c[3]) \
        : "r"(a0),"r"(a1),"r"(a2),"r"(a3), "r"(b0),"r"(b1))
#define IMMA16832(c, a0,a1,a2,a3, b0,b1) \
    asm volatile("mma.sync.aligned.m16n8k32.row.col.s32.s8.s8.s32 " \
        "{%0,%1,%2,%3}, {%4,%5,%6,%7}, {%8,%9}, {%0,%1,%2,%3};" \
        : "+r"(c[0]),"+r"(c[1]),"+r"(c[2]),"+r"(c[3]) \
        : "r"(a0),"r"(a1),"r"(a2),"r"(a3), "r"(b0),"r"(b1))

__device__ __forceinline__ uint32_t pack_bf2(float a, float b) {
    __nv_bfloat162 t = __floats2bfloat162_rn(a, b);
    return *reinterpret_cast<uint32_t*>(&t);
}
__device__ __forceinline__ void split_val(float f, bf16& h, bf16& l) {
    h = __float2bfloat16(f);
    l = __float2bfloat16(f - __bfloat162float(h));
}
__device__ __forceinline__ void quant2(float v, float invs, int8_t& q1, int8_t& q0) {
    float y = v * invs;                       // in [-127,127]
    int a1 = __float2int_rn(y);
    int a0 = __float2int_rn((y - (float)a1) * 256.0f);
    a0 = max(-127, min(127, a0));
    q1 = (int8_t)a1; q0 = (int8_t)a0;
}

// ---------------- weight prep ------------------------------------------------
__global__ void zscale_kernel() {
    int i = blockIdx.x * 256 + threadIdx.x;     // grid 16 -> 4096
    if (i < DM) { g_bq[i] = 0; g_bk[i] = 0; g_bv[i] = 0; g_bo[i] = 0; g_bu[i] = 0; }
    g_bi[i] = 0;
}

// per-n absmax for QKV ([h,d,k] gathered as column n=h*64+k of [d,n])
__global__ void colmax_qkv_kernel(const float* __restrict__ wq,
                                  const float* __restrict__ wk,
                                  const float* __restrict__ wv) {
    int n = blockIdx.x * 256 + threadIdx.x;     // grid (4, 8)
    int base = (n >> 6) * (DM * DH) + (n & 63);
    int d0 = blockIdx.y * 128;
    float mq = 0, mk = 0, mv = 0;
    for (int d = d0; d < d0 + 128; d++) {
        int idx = base + d * DH;
        mq = fmaxf(mq, fabsf(wq[idx]));
        mk = fmaxf(mk, fabsf(wk[idx]));
        mv = fmaxf(mv, fabsf(wv[idx]));
    }
    atomicMax(&g_bq[n], __float_as_uint(mq));
    atomicMax(&g_bk[n], __float_as_uint(mk));
    atomicMax(&g_bv[n], __float_as_uint(mv));
}

// per-column absmax of src [Rr, Cc]  (column c = output row n)
__global__ void colmax_kernel(const float* __restrict__ src, unsigned* bits,
                              int Rr, int Cc) {
    int c = blockIdx.x * 256 + threadIdx.x;
    int chunk = Rr >> 3;
    int r0 = blockIdx.y * chunk;
    float m = 0;
    for (int r = r0; r < r0 + chunk; r++)
        m = fmaxf(m, fabsf(src[(size_t)r * Cc + c]));
    atomicMax(&bits[c], __float_as_uint(m));
}

// QKV: gather + transpose + quantize -> [n=1024][K=1024] int8 hi/lo
__global__ void qtrans_qkv_kernel(const float* __restrict__ w,
                                  int8_t* o1, int8_t* o0,
                                  const unsigned* __restrict__ bits) {
    __shared__ float tsm[32][33];
    int n0 = blockIdx.x * 32, d0 = blockIdx.y * 32;
    int x = threadIdx.x & 31, y = threadIdx.x >> 5;
    int h = n0 >> 6, kb = n0 & 63;
    #pragma unroll
    for (int j = 0; j < 4; j++) {
        int d = d0 + y * 4 + j;
        tsm[y * 4 + j][x] = w[h * (DM * DH) + d * DH + kb + x];
    }
    __syncthreads();
    #pragma unroll
    for (int j = 0; j < 4; j++) {
        int n = n0 + y * 4 + j;
        float amax = fmaxf(__uint_as_float(bits[n]), 1e-20f);
        float invs = 127.0f / amax;
        int8_t q1, q0; quant2(tsm[x][y * 4 + j], invs, q1, q0);
        size_t o = (size_t)n * DM + d0 + x;
        o1[o] = q1; o0[o] = q0;
    }
}

// generic: src [Rr,Cc] fp32 -> transpose+quantize [Cc,Rr] int8 hi/lo
__global__ void qtrans_kernel(const float* __restrict__ src,
                              int8_t* o1, int8_t* o0,
                              const unsigned* __restrict__ bits, int Rr, int Cc) {
    __shared__ float tsm[32][33];
    int c0 = blockIdx.x * 32, r0 = blockIdx.y * 32;
    int x = threadIdx.x & 31, y = threadIdx.x >> 5;
    #pragma unroll
    for (int j = 0; j < 4; j++)
        tsm[y * 4 + j][x] = src[(size_t)(r0 + y * 4 + j) * Cc + c0 + x];
    __syncthreads();
    #pragma unroll
    for (int j = 0; j < 4; j++) {
        int n = c0 + y * 4 + j;
        float amax = fmaxf(__uint_as_float(bits[n]), 1e-20f);
        float invs = 127.0f / amax;
        int8_t q1, q0; quant2(tsm[x][y * 4 + j], invs, q1, q0);
        size_t o = (size_t)n * Rr + r0 + x;
        o1[o] = q1; o0[o] = q0;
    }
}

// ---------------- layernorm + row-quantize -----------------------------------
__global__ void ln_q_kernel(const float* __restrict__ x, const float* __restrict__ w,
                            const float* __restrict__ b,
                            int8_t* __restrict__ d1, int8_t* __restrict__ d0,
                            float* __restrict__ sc) {
    int row = blockIdx.x;
    int t = threadIdx.x;
    const float4 xv = *(const float4*)(x + (size_t)row * DM + t * 4);
    float s  = xv.x + xv.y + xv.z + xv.w;
    float ss = xv.x*xv.x + xv.y*xv.y + xv.z*xv.z + xv.w*xv.w;
    #pragma unroll
    for (int o = 16; o; o >>= 1) {
        s  += __shfl_xor_sync(0xffffffffu, s,  o);
        ss += __shfl_xor_sync(0xffffffffu, ss, o);
    }
    __shared__ float sb[8], sb2[8];
    int wid = t >> 5, lane = t & 31;
    if (lane == 0) { sb[wid] = s; sb2[wid] = ss; }
    __syncthreads();
    if (wid == 0) {
        s  = sb[lane & 7];
        ss = sb2[lane & 7];
        #pragma unroll
        for (int o = 4; o; o >>= 1) {
            s  += __shfl_xor_sync(0xffffffffu, s,  o);
            ss += __shfl_xor_sync(0xffffffffu, ss, o);
        }
        if (lane == 0) { sb[0] = s; sb2[0] = ss; }
    }
    __syncthreads();
    float mean = sb[0] * (1.0f / DM);
    float var  = sb2[0] * (1.0f / DM) - mean * mean;
    float rstd = rsqrtf(var + 1e-5f);
    float4 wv4 = *(const float4*)(w + t * 4);
    float4 bv4 = *(const float4*)(b + t * 4);
    float o0 = (xv.x - mean) * rstd * wv4.x + bv4.x;
    float o1 = (xv.y - mean) * rstd * wv4.y + bv4.y;
    float o2 = (xv.z - mean) * rstd * wv4.z + bv4.z;
    float o3 = (xv.w - mean) * rstd * wv4.w + bv4.w;

    // row absmax
    float am = fmaxf(fmaxf(fabsf(o0), fabsf(o1)), fmaxf(fabsf(o2), fabsf(o3)));
    #pragma unroll
    for (int o = 16; o; o >>= 1) am = fmaxf(am, __shfl_xor_sync(0xffffffffu, am, o));
    __syncthreads();
    if (lane == 0) sb[wid] = am;
    __syncthreads();
    if (wid == 0) {
        float mm = sb[lane & 7];
        #pragma unroll
        for (int o = 4; o; o >>= 1) mm = fmaxf(mm, __shfl_xor_sync(0xffffffffu, mm, o));
        if (lane == 0) sb[0] = mm;
    }
    __syncthreads();
    float amax = fmaxf(sb[0], 1e-20f);
    if (t == 0) sc[row] = amax * (1.0f / 127.0f);
    float invs = 127.0f / amax;
    int8_t a1[4], a0[4];
    quant2(o0, invs, a1[0], a0[0]);
    quant2(o1, invs, a1[1], a0[1]);
    quant2(o2, invs, a1[2], a0[2]);
    quant2(o3, invs, a1[3], a0[3]);
    size_t base = (size_t)row * DM + t * 4;
    *(char4*)(d1 + base) = make_char4(a1[0], a1[1], a1[2], a1[3]);
    *(char4*)(d0 + base) = make_char4(a0[0], a0[1], a0[2], a0[3]);
}

// ---------------- generic row quantize (z, relu acts) ------------------------
__global__ void rowquant_kernel(const float* __restrict__ src,
                                int8_t* __restrict__ d1, int8_t* __restrict__ d0,
                                float* __restrict__ sc, int K) {
    int row = blockIdx.x, t = threadIdx.x;
    int lane = t & 31, wid = t >> 5;
    const float* p = src + (size_t)row * K;
    int nc = K >> 10;                     // chunks of 1024 (1 or 4)
    float v[16];
    float am = 0;
    for (int c = 0; c < nc; c++) {
        float4 f = *(const float4*)(p + c * 1024 + t * 4);
        v[c*4+0] = f.x; v[c*4+1] = f.y; v[c*4+2] = f.z; v[c*4+3] = f.w;
        am = fmaxf(am, fmaxf(fmaxf(fabsf(f.x), fabsf(f.y)), fmaxf(fabsf(f.z), fabsf(f.w))));
    }
    #pragma unroll
    for (int o = 16; o; o >>= 1) am = fmaxf(am, __shfl_xor_sync(0xffffffffu, am, o));
    __shared__ float sm8[8];
    if (lane == 0) sm8[wid] = am;
    __syncthreads();
    if (wid == 0) {
        float mm = sm8[lane & 7];
        #pragma unroll
        for (int o = 4; o; o >>= 1) mm = fmaxf(mm, __shfl_xor_sync(0xffffffffu, mm, o));
        if (lane == 0) sm8[0] = mm;
    }
    __syncthreads();
    float amax = fmaxf(sm8[0], 1e-20f);
    if (t == 0) sc[row] = amax * (1.0f / 127.0f);
    float invs = 127.0f / amax;
    for (int c = 0; c < nc; c++) {
        int8_t a1[4], a0[4];
        #pragma unroll
        for (int e = 0; e < 4; e++) quant2(v[c*4+e], invs, a1[e], a0[e]);
        size_t base = (size_t)row * K + c * 1024 + t * 4;
        *(char4*)(d1 + base) = make_char4(a1[0], a1[1], a1[2], a1[3]);
        *(char4*)(d0 + base) = make_char4(a0[0], a0[1], a0[2], a0[3]);
    }
}

// ---------------- int8 tensor-core GEMM --------------------------------------
// A hi/lo int8 [M,K] (per-row scale sA), B hi/lo int8 [N,K] (per-row absmax bits).
// C = sA[m]*sB[n]*(H + M/256) + bias, 3 IMMA passes per k32.
// CTA 128x128, k-stage 64, 8 warps (2x4), warp tile 64x32.
// MODE 1: scatter [b,h,s,dh]; MODE 2: +R fp32; MODE 3: relu fp32.
#define QPITCH 80
#define QA_SZ  (128*QPITCH)       // 10240 bytes per array per stage
#define QSTAGE (4*QA_SZ)          // 40960
#define IG_SMEM (2*QSTAGE)        // 81920

template <int MODE>
__global__ __launch_bounds__(256, 1)
void igemm_kernel(const int8_t* __restrict__ A1, const int8_t* __restrict__ A0,
                  const int8_t* __restrict__ B1, const int8_t* __restrict__ B0,
                  const float* __restrict__ sA, const unsigned* __restrict__ sBb,
                  const float* __restrict__ bias, const float* __restrict__ R,
                  float* __restrict__ C, int M, int N, int K) {
    extern __shared__ __align__(16) char qs[];
    uint32_t s_base = smem_u32(qs);

    int tid = threadIdx.x;
    int lane = tid & 31, w = tid >> 5;
    int wm = w >> 2, wn = w & 3;
    int m0 = blockIdx.y * 128, n0 = blockIdx.x * 128;

    int H[4][4][4], Mm[4][4][4];
    #pragma unroll
    for (int i = 0; i < 4; i++)
        #pragma unroll
        for (int j = 0; j < 4; j++)
            #pragma unroll
            for (int c = 0; c < 4; c++) { H[i][j][c] = 0; Mm[i][j][c] = 0; }

    auto load_stage = [&](int k0, int st) {
        uint32_t sb = s_base + (uint32_t)st * QSTAGE;
        #pragma unroll
        for (int h = 0; h < 2; h++) {            // A: 512 chunks
            int idx = tid + h * 256;
            int r = idx >> 2, c = idx & 3;
            uint32_t off = (uint32_t)(r * QPITCH + c * 16);
            cp16(sb + off,          A1 + (size_t)(m0 + r) * K + k0 + c * 16);
            cp16(sb + QA_SZ + off,  A0 + (size_t)(m0 + r) * K + k0 + c * 16);
        }
        #pragma unroll
        for (int h = 0; h < 2; h++) {            // B: 512 chunks
            int idx = tid + h * 256;
            int r = idx >> 2, c = idx & 3;
            uint32_t off = (uint32_t)(r * QPITCH + c * 16);
            cp16(sb + 2*QA_SZ + off, B1 + (size_t)(n0 + r) * K + k0 + c * 16);
            cp16(sb + 3*QA_SZ + off, B0 + (size_t)(n0 + r) * K + k0 + c * 16);
        }
    };

    int nk = K >> 6;
    load_stage(0, 0);
    CP_COMMIT();

    for (int kt = 0; kt < nk; kt++) {
        int st = kt & 1;
        if (kt + 1 < nk) {
            load_stage((kt + 1) << 6, st ^ 1);
            CP_COMMIT();
            CP_WAIT1();
        } else {
            CP_WAIT0();
        }
        __syncthreads();

        uint32_t so = s_base + (uint32_t)st * QSTAGE;
        #pragma unroll
        for (int ks = 0; ks < 2; ks++) {
            uint32_t b1r[8], b0r[8];
            #pragma unroll
            for (int jp = 0; jp < 2; jp++) {
                uint32_t addrB = so + 2*QA_SZ
                    + (uint32_t)((wn*32 + jp*16 + (lane & 7) + ((lane >> 4) & 1) * 8) * QPITCH
                                 + ((lane >> 3) & 1) * 16 + ks * 32);
                LDSM_X4(b1r[jp*4+0], b1r[jp*4+1], b1r[jp*4+2], b1r[jp*4+3], addrB);
                LDSM_X4(b0r[jp*4+0], b0r[jp*4+1], b0r[jp*4+2], b0r[jp*4+3], addrB + QA_SZ);
            }
            #pragma unroll
            for (int i = 0; i < 4; i++) {
                uint32_t a1x0,a1x1,a1x2,a1x3, a0x0,a0x1,a0x2,a0x3;
                uint32_t addrA = so
                    + (uint32_t)((wm*64 + i*16 + (lane & 15)) * QPITCH
                                 + ((lane >> 4) & 1) * 16 + ks * 32);
                LDSM_X4(a1x0, a1x1, a1x2, a1x3, addrA);
                LDSM_X4(a0x0, a0x1, a0x2, a0x3, addrA + QA_SZ);
                #pragma unroll
                for (int j = 0; j < 4; j++) {
                    IMMA16832(H[i][j],  a1x0,a1x1,a1x2,a1x3, b1r[j*2], b1r[j*2+1]);
                    IMMA16832(Mm[i][j], a1x0,a1x1,a1x2,a1x3, b0r[j*2], b0r[j*2+1]);
                    IMMA16832(Mm[i][j], a0x0,a0x1,a0x2,a0x3, b1r[j*2], b1r[j*2+1]);
                }
            }
        }
        __syncthreads();
    }

    // ---- epilogue: dequant + bias + MODE ----
    int gid = lane >> 2;
    int tid4 = lane & 3;
    #pragma unroll
    for (int i = 0; i < 4; i++) {
        #pragma unroll
        for (int j = 0; j < 4; j++) {
            #pragma unroll
            for (int c = 0; c < 4; c++) {
                int m = m0 + wm * 64 + i * 16 + gid + (c >> 1) * 8;
                int n = n0 + wn * 32 + j * 8 + tid4 * 2 + (c & 1);
                float sB = __uint_as_float(sBb[n]) * (1.0f / 127.0f);
                float val = sA[m] * sB *
                            (__int2float_rn(H[i][j][c]) + __int2float_rn(Mm[i][j][c]) * (1.0f/256.0f))
                            + bias[n];
                if (MODE == 1) {
                    int bb = m >> 11;
                    int sq = m & (SQ - 1);
                    int h  = n >> 6;
                    int dk = n & 63;
                    C[(((size_t)(bb * NH + h)) * SQ + sq) * DH + dk] = val;
                } else if (MODE == 2) {
                    C[(size_t)m * N + n] = val + R[(size_t)m * N + n];
                } else {
                    C[(size_t)m * N + n] = fmaxf(val, 0.0f);
                }
            }
        }
    }
}

// ---------------- tensor-core flash attention (bf16 mma.sync) ----------------
#define FBM 128
#define FBN 64
#define FPITCH 72

__global__ __launch_bounds__(256, 1)
void flashmma_kernel(const float* __restrict__ q, const float* __restrict__ k,
                     const float* __restrict__ v, float* __restrict__ z) {
    extern __shared__ bf16 fsm[];
    bf16* Qh = fsm;
    bf16* Ql = Qh + FBM * FPITCH;
    bf16* Kh = Ql + FBM * FPITCH;
    bf16* Kl = Kh + FBN * FPITCH;
    bf16* Vh = Kl + FBN * FPITCH;
    bf16* Vl = Vh + FBN * FPITCH;

    int qt = blockIdx.x, bh = blockIdx.y;
    int bb = bh >> 4, hh = bh & 15;
    int tid = threadIdx.x, lane = tid & 31, w = tid >> 5;
    int gid = lane >> 2, qd = lane & 3;

    const float* qbase = q + ((size_t)bh * SQ + (size_t)qt * FBM) * DH;
    const float* kbase = k + (size_t)bh * SQ * DH;
    const float* vbase = v + (size_t)bh * SQ * DH;

    #pragma unroll
    for (int j = 0; j < 8; j++) {
        int idx = tid + j * 256;
        int r = idx >> 4, c = (idx & 15) * 4;
        float4 t4 = *(const float4*)(qbase + (size_t)r * DH + c);
        float f[4] = {t4.x, t4.y, t4.z, t4.w};
        #pragma unroll
        for (int e = 0; e < 4; e++)
            split_val(f[e], Qh[r * FPITCH + c + e], Ql[r * FPITCH + c + e]);
    }
    __syncthreads();

    uint32_t qh[4][4], ql[4][4];
    #pragma unroll
    for (int kc = 0; kc < 4; kc++) {
        uint32_t a1 = smem_u32(&Qh[(w * 16 + (lane & 15)) * FPITCH + kc * 16 + (lane >> 4) * 8]);
        LDSM_X4(qh[kc][0], qh[kc][1], qh[kc][2], qh[kc][3], a1);
        uint32_t a2 = smem_u32(&Ql[(w * 16 + (lane & 15)) * FPITCH + kc * 16 + (lane >> 4) * 8]);
        LDSM_X4(ql[kc][0], ql[kc][1], ql[kc][2], ql[kc][3], a2);
    }

    float o[8][4];
    #pragma unroll
    for (int j = 0; j < 8; j++)
        #pragma unroll
        for (int c = 0; c < 4; c++) o[j][c] = 0.0f;
    float mi0 = -1e30f, mi1 = -1e30f, li0 = 0.0f, li1 = 0.0f;

    int row0g = qt * FBM + w * 16 + gid;
    int row1g = row0g + 8;

    int nkt = 2 * qt + 2;
    for (int kt = 0; kt < nkt; kt++) {
        __syncthreads();
        #pragma unroll
        for (int j = 0; j < 4; j++) {
            int idx = tid + j * 256;
            int r = idx >> 4, c = (idx & 15) * 4;
            float4 t4 = *(const float4*)(kbase + ((size_t)kt * FBN + r) * DH + c);
            float f[4] = {t4.x, t4.y, t4.z, t4.w};
            #pragma unroll
            for (int e = 0; e < 4; e++)
                split_val(f[e], Kh[r * FPITCH + c + e], Kl[r * FPITCH + c + e]);
            float4 u4 = *(const float4*)(vbase + ((size_t)kt * FBN + r) * DH + c);
            float g[4] = {u4.x, u4.y, u4.z, u4.w};
            #pragma unroll
            for (int e = 0; e < 4; e++)
                split_val(g[e], Vh[r * FPITCH + c + e], Vl[r * FPITCH + c + e]);
        }
        __syncthreads();

        float s[8][4];
        #pragma unroll
        for (int j = 0; j < 8; j++)
            #pragma unroll
            for (int c = 0; c < 4; c++) s[j][c] = 0.0f;

        #pragma unroll
        for (int kc = 0; kc < 4; kc++) {
            #pragma unroll
            for (int jj = 0; jj < 4; jj++) {
                uint32_t addr_h = smem_u32(&Kh[((jj * 2 + (lane >> 4)) * 8 + (lane & 7)) * FPITCH
                                               + kc * 16 + ((lane >> 3) & 1) * 8]);
                uint32_t addr_l = smem_u32(&Kl[((jj * 2 + (lane >> 4)) * 8 + (lane & 7)) * FPITCH
                                               + kc * 16 + ((lane >> 3) & 1) * 8]);
                uint32_t kh0, kh1, kh2, kh3, kl0, kl1, kl2, kl3;
                LDSM_X4(kh0, kh1, kh2, kh3, addr_h);
                LDSM_X4(kl0, kl1, kl2, kl3, addr_l);
                MMA16816(s[jj*2  ], qh[kc][0], qh[kc][1], qh[kc][2], qh[kc][3], kh0, kh1);
                MMA16816(s[jj*2  ], qh[kc][0], qh[kc][1], qh[kc][2], qh[kc][3], kl0, kl1);
                MMA16816(s[jj*2  ], ql[kc][0], ql[kc][1], ql[kc][2], ql[kc][3], kh0, kh1);
                MMA16816(s[jj*2+1], qh[kc][0], qh[kc][1], qh[kc][2], qh[kc][3], kh2, kh3);
                MMA16816(s[jj*2+1], qh[kc][0], qh[kc][1], qh[kc][2], qh[kc][3], kl2, kl3);
                MMA16816(s[jj*2+1], ql[kc][0], ql[kc][1], ql[kc][2], ql[kc][3], kh2, kh3);
            }
        }

        #pragma unroll
        for (int j = 0; j < 8; j++)
            #pragma unroll
            for (int c = 0; c < 4; c++) s[j][c] *= 0.125f;

        if (kt * 64 + 63 > qt * 128 + w * 16) {
            #pragma unroll
            for (int j = 0; j < 8; j++) {
                int col = kt * 64 + j * 8 + qd * 2;
                if (col     > row0g) s[j][0] = -1e30f;
                if (col + 1 > row0g) s[j][1] = -1e30f;
                if (col     > row1g) s[j][2] = -1e30f;
                if (col + 1 > row1g) s[j][3] = -1e30f;
            }
        }

        float rm0 = -1e30f, rm1 = -1e30f;
        #pragma unroll
        for (int j = 0; j < 8; j++) {
            rm0 = fmaxf(rm0, fmaxf(s[j][0], s[j][1]));
            rm1 = fmaxf(rm1, fmaxf(s[j][2], s[j][3]));
        }
        rm0 = fmaxf(rm0, __shfl_xor_sync(0xffffffffu, rm0, 1));
        rm0 = fmaxf(rm0, __shfl_xor_sync(0xffffffffu, rm0, 2));
        rm1 = fmaxf(rm1, __shfl_xor_sync(0xffffffffu, rm1, 1));
        rm1 = fmaxf(rm1, __shfl_xor_sync(0xffffffffu, rm1, 2));
        float mn0 = fmaxf(mi0, rm0), mn1 = fmaxf(mi1, rm1);
        float al0 = __expf(mi0 - mn0), al1 = __expf(mi1 - mn1);
        mi0 = mn0; mi1 = mn1;
        float rs0 = 0.0f, rs1 = 0.0f;
        #pragma unroll
        for (int j = 0; j < 8; j++) {
            s[j][0] = __expf(s[j][0] - mn0);
            s[j][1] = __expf(s[j][1] - mn0);
            s[j][2] = __expf(s[j][2] - mn1);
            s[j][3] = __expf(s[j][3] - mn1);
            rs0 += s[j][0] + s[j][1];
            rs1 += s[j][2] + s[j][3];
        }
        rs0 += __shfl_xor_sync(0xffffffffu, rs0, 1);
        rs0 += __shfl_xor_sync(0xffffffffu, rs0, 2);
        rs1 += __shfl_xor_sync(0xffffffffu, rs1, 1);
        rs1 += __shfl_xor_sync(0xffffffffu, rs1, 2);
        li0 = li0 * al0 + rs0;
        li1 = li1 * al1 + rs1;

        #pragma unroll
        for (int j = 0; j < 8; j++) {
            o[j][0] *= al0; o[j][1] *= al0;
            o[j][2] *= al1; o[j][3] *= al1;
        }

        uint32_t pa[4][4];
        #pragma unroll
        for (int kc = 0; kc < 4; kc++) {
            pa[kc][0] = pack_bf2(s[2*kc  ][0], s[2*kc  ][1]);
            pa[kc][1] = pack_bf2(s[2*kc  ][2], s[2*kc  ][3]);
            pa[kc][2] = pack_bf2(s[2*kc+1][0], s[2*kc+1][1]);
            pa[kc][3] = pack_bf2(s[2*kc+1][2], s[2*kc+1][3]);
        }

        #pragma unroll
        for (int kc = 0; kc < 4; kc++) {
            #pragma unroll
            for (int jj = 0; jj < 4; jj++) {
                uint32_t addr_h = smem_u32(&Vh[(kc * 16 + (lane & 7) + ((lane >> 3) & 1) * 8) * FPITCH
                                               + (jj * 2 + (lane >> 4)) * 8]);
                uint32_t addr_l = smem_u32(&Vl[(kc * 16 + (lane & 7) + ((lane >> 3) & 1) * 8) * FPITCH
                                               + (jj * 2 + (lane >> 4)) * 8]);
                uint32_t vh0, vh1, vh2, vh3, vl0, vl1, vl2, vl3;
                LDSM_X4_T(vh0, vh1, vh2, vh3, addr_h);
                LDSM_X4_T(vl0, vl1, vl2, vl3, addr_l);
                MMA16816(o[jj*2  ], pa[kc][0], pa[kc][1], pa[kc][2], pa[kc][3], vh0, vh1);
                MMA16816(o[jj*2  ], pa[kc][0], pa[kc][1], pa[kc][2], pa[kc][3], vl0, vl1);
                MMA16816(o[jj*2+1], pa[kc][0], pa[kc][1], pa[kc][2], pa[kc][3], vh2, vh3);
                MMA16816(o[jj*2+1], pa[kc][0], pa[kc][1], pa[kc][2], pa[kc][3], vl2, vl3);
            }
        }
    }

    float inv0 = 1.0f / li0, inv1 = 1.0f / li1;
    float* zb = z + ((size_t)bb * SQ + (size_t)qt * FBM + w * 16) * DM + hh * DH;
    #pragma unroll
    for (int j = 0; j < 8; j++) {
        int col = j * 8 + qd * 2;
        *(float2*)(zb + (size_t)gid * DM + col)       = make_float2(o[j][0] * inv0, o[j][1] * inv0);
        *(float2*)(zb + (size_t)(gid + 8) * DM + col) = make_float2(o[j][2] * inv1, o[j][3] * inv1);
    }
}

// ---------------- host launcher ---------------------------------------------
template <typename T>
static T* sym_addr(const void* symbol) {
    void* p = nullptr;
    cudaGetSymbolAddress(&p, symbol);
    return (T*)p;
}

extern "C" void kernel_launch(void* const* d_in, const int* in_sizes, int n_in,
                              void* d_out, int out_size) {
    const float* resid_pre = (const float*)d_in[0];
    const float* ln1_w = (const float*)d_in[1];
    const float* ln1_b = (const float*)d_in[2];
    const float* W_Q   = (const float*)d_in[3];
    const float* b_Q   = (const float*)d_in[4];
    const float* W_K   = (const float*)d_in[5];
    const float* b_K   = (const float*)d_in[6];
    const float* W_V   = (const float*)d_in[7];
    const float* b_V   = (const float*)d_in[8];
    const float* W_O   = (const float*)d_in[9];
    const float* b_O   = (const float*)d_in[10];
    const float* ln2_w = (const float*)d_in[11];
    const float* ln2_b = (const float*)d_in[12];
    const float* W_in  = (const float*)d_in[13];
    const float* b_in  = (const float*)d_in[14];
    const float* W_out = (const float*)d_in[15];
    const float* b_out = (const float*)d_in[16];
    float* out = (float*)d_out;

    float* qb    = sym_addr<float>(g_q);
    float* kb    = sym_addr<float>(g_k);
    float* vb    = sym_addr<float>(g_v);
    float* rmid  = sym_addr<float>(g_rmid);
    float* zbuf  = sym_addr<float>(g_z);
    float* actf  = sym_addr<float>(g_actf);

    int8_t* xa1 = sym_addr<int8_t>(g_xa1); int8_t* xa0 = sym_addr<int8_t>(g_xa0);
    int8_t* z1  = sym_addr<int8_t>(g_z1);  int8_t* z0  = sym_addr<int8_t>(g_z0);
    int8_t* h21 = sym_addr<int8_t>(g_h21); int8_t* h20 = sym_addr<int8_t>(g_h20);
    int8_t* ac1 = sym_addr<int8_t>(g_ac1); int8_t* ac0 = sym_addr<int8_t>(g_ac0);
    float* sx = sym_addr<float>(g_sx); float* sz = sym_addr<float>(g_sz);
    float* sh = sym_addr<float>(g_sh); float* sa = sym_addr<float>(g_sa);

    int8_t* wq1 = sym_addr<int8_t>(g_wq1); int8_t* wq0 = sym_addr<int8_t>(g_wq0);
    int8_t* wk1 = sym_addr<int8_t>(g_wk1); int8_t* wk0 = sym_addr<int8_t>(g_wk0);
    int8_t* wv1 = sym_addr<int8_t>(g_wv1); int8_t* wv0 = sym_addr<int8_t>(g_wv0);
    int8_t* wo1 = sym_addr<int8_t>(g_wo1); int8_t* wo0 = sym_addr<int8_t>(g_wo0);
    int8_t* wi1 = sym_addr<int8_t>(g_wi1); int8_t* wi0 = sym_addr<int8_t>(g_wi0);
    int8_t* wu1 = sym_addr<int8_t>(g_wu1); int8_t* wu0 = sym_addr<int8_t>(g_wu0);
    unsigned* bq = sym_addr<unsigned>(g_bq); unsigned* bk = sym_addr<unsigned>(g_bk);
    unsigned* bv = sym_addr<unsigned>(g_bv); unsigned* bo = sym_addr<unsigned>(g_bo);
    unsigned* bi = sym_addr<unsigned>(g_bi); unsigned* bu = sym_addr<unsigned>(g_bu);

    cudaFuncSetAttribute(igemm_kernel<1>, cudaFuncAttributeMaxDynamicSharedMemorySize, IG_SMEM);
    cudaFuncSetAttribute(igemm_kernel<2>, cudaFuncAttributeMaxDynamicSharedMemorySize, IG_SMEM);
    cudaFuncSetAttribute(igemm_kernel<3>, cudaFuncAttributeMaxDynamicSharedMemorySize, IG_SMEM);

    // 1. weight prep: absmax + transpose-quantize
    zscale_kernel<<<16, 256>>>();
    colmax_qkv_kernel<<<dim3(4, 8), 256>>>(W_Q, W_K, W_V);
    colmax_kernel<<<dim3(4, 8), 256>>>(W_O,  bo, DM,   DM);
    colmax_kernel<<<dim3(16, 8), 256>>>(W_in, bi, DM,   DMLP);
    colmax_kernel<<<dim3(4, 8), 256>>>(W_out, bu, DMLP, DM);
    qtrans_qkv_kernel<<<dim3(32, 32), 256>>>(W_Q, wq1, wq0, bq);
    qtrans_qkv_kernel<<<dim3(32, 32), 256>>>(W_K, wk1, wk0, bk);
    qtrans_qkv_kernel<<<dim3(32, 32), 256>>>(W_V, wv1, wv0, bv);
    qtrans_kernel<<<dim3(32, 32), 256>>>(W_O,  wo1, wo0, bo, DM,   DM);
    qtrans_kernel<<<dim3(128, 32), 256>>>(W_in, wi1, wi0, bi, DM,   DMLP);
    qtrans_kernel<<<dim3(32, 128), 256>>>(W_out, wu1, wu0, bu, DMLP, DM);

    // 2. LN1 + row-quant
    ln_q_kernel<<<NTOK, 256>>>(resid_pre, ln1_w, ln1_b, xa1, xa0, sx);

    // 3. QKV projections (int8 IMMA, scatter to [b,h,s,dh] fp32)
    dim3 gq(DM / 128, NTOK / 128);          // (8, 32)
    igemm_kernel<1><<<gq, 256, IG_SMEM>>>(xa1, xa0, wq1, wq0, sx, bq, b_Q, nullptr, qb, NTOK, DM, DM);
    igemm_kernel<1><<<gq, 256, IG_SMEM>>>(xa1, xa0, wk1, wk0, sx, bk, b_K, nullptr, kb, NTOK, DM, DM);
    igemm_kernel<1><<<gq, 256, IG_SMEM>>>(xa1, xa0, wv1, wv0, sx, bv, b_V, nullptr, vb, NTOK, DM, DM);

    // 4. flash attention (bf16 mma.sync) -> z fp32
    const size_t fl_smem = (size_t)(2*FBM + 4*FBN) * FPITCH * sizeof(bf16); // 73728
    cudaFuncSetAttribute(flashmma_kernel,
                         cudaFuncAttributeMaxDynamicSharedMemorySize, (int)fl_smem);
    flashmma_kernel<<<dim3(SQ / FBM, BT * NH), 256, fl_smem>>>(qb, kb, vb, zbuf);

    // 5. quantize z, O-proj + residual -> resid_mid
    rowquant_kernel<<<NTOK, 256>>>(zbuf, z1, z0, sz, DM);
    igemm_kernel<2><<<gq, 256, IG_SMEM>>>(z1, z0, wo1, wo0, sz, bo, b_O, resid_pre, rmid, NTOK, DM, DM);

    // 6. LN2 + row-quant
    ln_q_kernel<<<NTOK, 256>>>(rmid, ln2_w, ln2_b, h21, h20, sh);

    // 7. MLP in + ReLU -> fp32 acts, then row-quant
    dim3 gi(DMLP / 128, NTOK / 128);        // (32, 32)
    igemm_kernel<3><<<gi, 256, IG_SMEM>>>(h21, h20, wi1, wi0, sh, bi, b_in, nullptr, actf, NTOK, DMLP, DM);
    rowquant_kernel<<<NTOK, 256>>>(actf, ac1, ac0, sa, DMLP);

    // 8. MLP out + bias + residual -> output
    igemm_kernel<2><<<gq, 256, IG_SMEM>>>(ac1, ac0, wu1, wu0, sa, bu, b_out, rmid, out, NTOK, DM, DMLP);
}

// round 15
// speedup vs baseline: 2.9281x; 2.9281x over previous
#include <cuda_runtime.h>
#include <cuda_bf16.h>
#include <cuda_fp16.h>
#include <stdint.h>
#include <cstdint>
#include <math.h>

// Problem constants
#define SQ   2048
#define DM   1024
#define NH   16
#define DH   64
#define BT   2
#define NTOK (BT*SQ)      // 4096
#define DMLP 4096

typedef __nv_bfloat16 bf16;

// ---------------- scratch (device globals; no allocations allowed) ----------
__device__ float g_xln [NTOK*DM];
__device__ float g_q   [NTOK*DM];      // [B,H,S,DH]
__device__ float g_k   [NTOK*DM];
__device__ float g_v   [NTOK*DM];
__device__ float g_z   [NTOK*DM];      // attn concat [tok, h*64+dh]
__device__ float g_rmid[NTOK*DM];
__device__ float g_h2  [NTOK*DM];
__device__ float g_act [NTOK*DMLP];
__device__ float g_wq  [DM*DM];        // repacked [d, h*64+k]
__device__ float g_wk  [DM*DM];
__device__ float g_wv  [DM*DM];

// ---------------- weight repack: [h,d,k] -> [d, h*64+k] ---------------------
__global__ void repack_kernel(const float* __restrict__ wq,
                              const float* __restrict__ wk,
                              const float* __restrict__ wv) {
    int idx = blockIdx.x * 256 + threadIdx.x;
    int d  = idx >> 10;
    int n  = idx & 1023;
    int h  = n >> 6;
    int kk = n & 63;
    int src = h * (DM * DH) + d * DH + kk;
    g_wq[idx] = wq[src];
    g_wk[idx] = wk[src];
    g_wv[idx] = wv[src];
}

// ---------------- layernorm: one block per row (1024 elems, 256 thr) --------
__global__ void ln_kernel(const float* __restrict__ x, const float* __restrict__ w,
                          const float* __restrict__ b, float* __restrict__ y) {
    int row = blockIdx.x;
    int t = threadIdx.x;
    const float4 xv = *(const float4*)(x + (size_t)row * DM + t * 4);
    float s  = xv.x + xv.y + xv.z + xv.w;
    float ss = xv.x*xv.x + xv.y*xv.y + xv.z*xv.z + xv.w*xv.w;
    #pragma unroll
    for (int o = 16; o; o >>= 1) {
        s  += __shfl_xor_sync(0xffffffffu, s,  o);
        ss += __shfl_xor_sync(0xffffffffu, ss, o);
    }
    __shared__ float sb[8], sb2[8];
    int wid = t >> 5, lane = t & 31;
    if (lane == 0) { sb[wid] = s; sb2[wid] = ss; }
    __syncthreads();
    if (wid == 0) {
        s  = sb[lane & 7];
        ss = sb2[lane & 7];
        #pragma unroll
        for (int o = 4; o; o >>= 1) {
            s  += __shfl_xor_sync(0xffffffffu, s,  o);
            ss += __shfl_xor_sync(0xffffffffu, ss, o);
        }
        if (lane == 0) { sb[0] = s; sb2[0] = ss; }
    }
    __syncthreads();
    float mean = sb[0] * (1.0f / DM);
    float var  = sb2[0] * (1.0f / DM) - mean * mean;
    float rstd = rsqrtf(var + 1e-5f);
    float4 wv4 = *(const float4*)(w + t * 4);
    float4 bv4 = *(const float4*)(b + t * 4);
    float4 o4;
    o4.x = (xv.x - mean) * rstd * wv4.x + bv4.x;
    o4.y = (xv.y - mean) * rstd * wv4.y + bv4.y;
    o4.z = (xv.z - mean) * rstd * wv4.z + bv4.z;
    o4.w = (xv.w - mean) * rstd * wv4.w + bv4.w;
    *(float4*)(y + (size_t)row * DM + t * 4) = o4;
}

// ---------------- mma helpers ------------------------------------------------
__device__ __forceinline__ uint32_t smem_u32(const void* p) {
    return (uint32_t)__cvta_generic_to_shared(p);
}

#define LDSM_X4(r0,r1,r2,r3,addr) \
    asm volatile("ldmatrix.sync.aligned.m8n8.x4.shared.b16 {%0,%1,%2,%3}, [%4];" \
        : "=r"(r0),"=r"(r1),"=r"(r2),"=r"(r3) : "r"(addr))

#define LDSM_X4_T(r0,r1,r2,r3,addr) \
    asm volatile("ldmatrix.sync.aligned.m8n8.x4.trans.shared.b16 {%0,%1,%2,%3}, [%4];" \
        : "=r"(r0),"=r"(r1),"=r"(r2),"=r"(r3) : "r"(addr))

// bf16 mma (flash attention)
#define MMA16816(c, a0,a1,a2,a3, b0,b1) \
    asm volatile("mma.sync.aligned.m16n8k16.row.col.f32.bf16.bf16.f32 " \
        "{%0,%1,%2,%3}, {%4,%5,%6,%7}, {%8,%9}, {%0,%1,%2,%3};" \
        : "+f"(c[0]),"+f"(c[1]),"+f"(c[2]),"+f"(c[3]) \
        : "r"(a0),"r"(a1),"r"(a2),"r"(a3), "r"(b0),"r"(b1))

// fp16 mma (GEMMs)
#define MMA16816H(c, a0,a1,a2,a3, b0,b1) \
    asm volatile("mma.sync.aligned.m16n8k16.row.col.f32.f16.f16.f32 " \
        "{%0,%1,%2,%3}, {%4,%5,%6,%7}, {%8,%9}, {%0,%1,%2,%3};" \
        : "+f"(c[0]),"+f"(c[1]),"+f"(c[2]),"+f"(c[3]) \
        : "r"(a0),"r"(a1),"r"(a2),"r"(a3), "r"(b0),"r"(b1))

__device__ __forceinline__ uint32_t pack_bf2(float a, float b) {
    __nv_bfloat162 t = __floats2bfloat162_rn(a, b);
    return *reinterpret_cast<uint32_t*>(&t);
}
__device__ __forceinline__ void split_bf(float f, bf16& h, bf16& l) {
    h = __float2bfloat16(f);
    l = __float2bfloat16(f - __bfloat162float(h));
}
__device__ __forceinline__ void split_h(float f, __half& h, __half& l) {
    h = __float2half_rn(f);
    l = __float2half_rn(f - __half2float(h));
}

// ---------------- tensor-core GEMM: fp16 2-pass (A hi/lo, B fp16) ------------
// C = A*B (+bias, epilogue by MODE), A fp32 [M,K] row-major, B fp32 [K,N] row-major.
// A = ah + al (fp16 each, ~22-bit capture); B rounded to fp16 (~2^-12 rel).
// acc = ah*B + al*B (2 MMA passes). Result error ~1e-4 relative.
// CTA tile 128x128x32, 8 warps (2x4), warp tile 64x32.
// MODE 1: scatter [b,h,s,dh] + bias; MODE 2: +bias+R; MODE 3: relu(+bias).
#define APAD 40
#define BPAD 136

template <int MODE>
__global__ __launch_bounds__(256, 2)
void hgemm_kernel(const float* __restrict__ A, const float* __restrict__ B,
                  const float* __restrict__ bias, const float* __restrict__ R,
                  float* __restrict__ C, int M, int N, int K) {
    __shared__ __align__(16) __half As[2][128][APAD];   // [hi/lo][m][k]
    __shared__ __align__(16) __half Bs[32][BPAD];       // [k][n] fp16 single

    int tid = threadIdx.x;
    int lane = tid & 31;
    int warp = tid >> 5;
    int wm = warp >> 2;        // 0..1
    int wn = warp & 3;         // 0..3
    int m0 = blockIdx.y * 128, n0 = blockIdx.x * 128;

    int ar = tid >> 3;         // 0..31  (A row base)
    int ac = (tid & 7) * 4;    // A k-col (float4)
    int br = tid >> 5;         // 0..7   (B k-row base)
    int bc = (tid & 31) * 4;   // B n-col (float4)

    float acc[4][4][4];
    #pragma unroll
    for (int i = 0; i < 4; i++)
        #pragma unroll
        for (int j = 0; j < 4; j++)
            #pragma unroll
            for (int c = 0; c < 4; c++) acc[i][j][c] = 0.0f;

    uint32_t a_base_hi = smem_u32(&As[0][wm*64 + (lane & 15)][(lane >> 4) * 8]);
    uint32_t a_base_lo = smem_u32(&As[1][wm*64 + (lane & 15)][(lane >> 4) * 8]);
    uint32_t b_base    = smem_u32(&Bs[lane & 15][wn*32 + (lane >> 4) * 8]);

    for (int k0 = 0; k0 < K; k0 += 32) {
        // ---- stage A tile (128x32) fp32 -> fp16 hi/lo smem ----
        #pragma unroll
        for (int q = 0; q < 4; q++) {
            int r = ar + q * 32;
            const float4 av = *(const float4*)(A + (size_t)(m0 + r) * K + k0 + ac);
            float f[4] = {av.x, av.y, av.z, av.w};
            #pragma unroll
            for (int e = 0; e < 4; e++) {
                __half h, l;
                split_h(f[e], h, l);
                As[0][r][ac + e] = h;
                As[1][r][ac + e] = l;
            }
        }
        // ---- stage B tile (32x128) fp32 -> fp16 smem ----
        #pragma unroll
        for (int q = 0; q < 4; q++) {
            int r = br + q * 8;
            const float4 bv = *(const float4*)(B + (size_t)(k0 + r) * N + n0 + bc);
            Bs[r][bc + 0] = __float2half_rn(bv.x);
            Bs[r][bc + 1] = __float2half_rn(bv.y);
            Bs[r][bc + 2] = __float2half_rn(bv.z);
            Bs[r][bc + 3] = __float2half_rn(bv.w);
        }
        __syncthreads();

        #pragma unroll
        for (int ks = 0; ks < 2; ks++) {
            uint32_t bh[8];
            {
                uint32_t off = (uint32_t)(ks * 16 * BPAD * 2);
                LDSM_X4_T(bh[0], bh[1], bh[2], bh[3], b_base + off);
                LDSM_X4_T(bh[4], bh[5], bh[6], bh[7], b_base + off + 16 * 2);
            }
            #pragma unroll
            for (int i = 0; i < 4; i++) {
                uint32_t ah0, ah1, ah2, ah3, al0, al1, al2, al3;
                uint32_t aoff = (uint32_t)((i * 16 * APAD + ks * 16) * 2);
                LDSM_X4(ah0, ah1, ah2, ah3, a_base_hi + aoff);
                LDSM_X4(al0, al1, al2, al3, a_base_lo + aoff);
                #pragma unroll
                for (int j = 0; j < 4; j++) {
                    MMA16816H(acc[i][j], ah0, ah1, ah2, ah3, bh[2*j], bh[2*j+1]);
                    MMA16816H(acc[i][j], al0, al1, al2, al3, bh[2*j], bh[2*j+1]);
                }
            }
        }
        __syncthreads();
    }

    // ---- epilogue ----
    int gid = lane >> 2;
    int tid4 = lane & 3;
    #pragma unroll
    for (int i = 0; i < 4; i++) {
        #pragma unroll
        for (int j = 0; j < 4; j++) {
            #pragma unroll
            for (int c = 0; c < 4; c++) {
                int m = m0 + wm * 64 + i * 16 + gid + (c >> 1) * 8;
                int n = n0 + wn * 32 + j * 8 + tid4 * 2 + (c & 1);
                float val = acc[i][j][c] + bias[n];
                if (MODE == 1) {
                    int bb = m >> 11;
                    int s  = m & (SQ - 1);
                    int h  = n >> 6;
                    int dk = n & 63;
                    C[(((size_t)(bb * NH + h)) * SQ + s) * DH + dk] = val;
                } else if (MODE == 2) {
                    C[(size_t)m * N + n] = val + R[(size_t)m * N + n];
                } else {
                    C[(size_t)m * N + n] = fmaxf(val, 0.0f);
                }
            }
        }
    }
}

// ---------------- tensor-core flash attention (bf16 3-pass, unchanged) -------
#define FBM 128
#define FBN 64
#define FPITCH 72

__global__ __launch_bounds__(256, 1)
void flashmma_kernel(const float* __restrict__ q, const float* __restrict__ k,
                     const float* __restrict__ v, float* __restrict__ z) {
    extern __shared__ bf16 fsm[];
    bf16* Qh = fsm;
    bf16* Ql = Qh + FBM * FPITCH;
    bf16* Kh = Ql + FBM * FPITCH;
    bf16* Kl = Kh + FBN * FPITCH;
    bf16* Vh = Kl + FBN * FPITCH;
    bf16* Vl = Vh + FBN * FPITCH;

    int qt = blockIdx.x, bh = blockIdx.y;
    int bb = bh >> 4, hh = bh & 15;
    int tid = threadIdx.x, lane = tid & 31, w = tid >> 5;
    int gid = lane >> 2, qd = lane & 3;

    const float* qbase = q + ((size_t)bh * SQ + (size_t)qt * FBM) * DH;
    const float* kbase = k + (size_t)bh * SQ * DH;
    const float* vbase = v + (size_t)bh * SQ * DH;

    #pragma unroll
    for (int j = 0; j < 8; j++) {
        int idx = tid + j * 256;
        int r = idx >> 4, c = (idx & 15) * 4;
        float4 t4 = *(const float4*)(qbase + (size_t)r * DH + c);
        float f[4] = {t4.x, t4.y, t4.z, t4.w};
        #pragma unroll
        for (int e = 0; e < 4; e++)
            split_bf(f[e], Qh[r * FPITCH + c + e], Ql[r * FPITCH + c + e]);
    }
    __syncthreads();

    uint32_t qh[4][4], ql[4][4];
    #pragma unroll
    for (int kc = 0; kc < 4; kc++) {
        uint32_t a1 = smem_u32(&Qh[(w * 16 + (lane & 15)) * FPITCH + kc * 16 + (lane >> 4) * 8]);
        LDSM_X4(qh[kc][0], qh[kc][1], qh[kc][2], qh[kc][3], a1);
        uint32_t a2 = smem_u32(&Ql[(w * 16 + (lane & 15)) * FPITCH + kc * 16 + (lane >> 4) * 8]);
        LDSM_X4(ql[kc][0], ql[kc][1], ql[kc][2], ql[kc][3], a2);
    }

    float o[8][4];
    #pragma unroll
    for (int j = 0; j < 8; j++)
        #pragma unroll
        for (int c = 0; c < 4; c++) o[j][c] = 0.0f;
    float mi0 = -1e30f, mi1 = -1e30f, li0 = 0.0f, li1 = 0.0f;

    int row0g = qt * FBM + w * 16 + gid;
    int row1g = row0g + 8;

    int nkt = 2 * qt + 2;
    for (int kt = 0; kt < nkt; kt++) {
        __syncthreads();
        #pragma unroll
        for (int j = 0; j < 4; j++) {
            int idx = tid + j * 256;
            int r = idx >> 4, c = (idx & 15) * 4;
            float4 t4 = *(const float4*)(kbase + ((size_t)kt * FBN + r) * DH + c);
            float f[4] = {t4.x, t4.y, t4.z, t4.w};
            #pragma unroll
            for (int e = 0; e < 4; e++)
                split_bf(f[e], Kh[r * FPITCH + c + e], Kl[r * FPITCH + c + e]);
            float4 u4 = *(const float4*)(vbase + ((size_t)kt * FBN + r) * DH + c);
            float g[4] = {u4.x, u4.y, u4.z, u4.w};
            #pragma unroll
            for (int e = 0; e < 4; e++)
                split_bf(g[e], Vh[r * FPITCH + c + e], Vl[r * FPITCH + c + e]);
        }
        __syncthreads();

        float s[8][4];
        #pragma unroll
        for (int j = 0; j < 8; j++)
            #pragma unroll
            for (int c = 0; c < 4; c++) s[j][c] = 0.0f;

        #pragma unroll
        for (int kc = 0; kc < 4; kc++) {
            #pragma unroll
            for (int jj = 0; jj < 4; jj++) {
                uint32_t addr_h = smem_u32(&Kh[((jj * 2 + (lane >> 4)) * 8 + (lane & 7)) * FPITCH
                                               + kc * 16 + ((lane >> 3) & 1) * 8]);
                uint32_t addr_l = smem_u32(&Kl[((jj * 2 + (lane >> 4)) * 8 + (lane & 7)) * FPITCH
                                               + kc * 16 + ((lane >> 3) & 1) * 8]);
                uint32_t kh0, kh1, kh2, kh3, kl0, kl1, kl2, kl3;
                LDSM_X4(kh0, kh1, kh2, kh3, addr_h);
                LDSM_X4(kl0, kl1, kl2, kl3, addr_l);
                MMA16816(s[jj*2  ], qh[kc][0], qh[kc][1], qh[kc][2], qh[kc][3], kh0, kh1);
                MMA16816(s[jj*2  ], qh[kc][0], qh[kc][1], qh[kc][2], qh[kc][3], kl0, kl1);
                MMA16816(s[jj*2  ], ql[kc][0], ql[kc][1], ql[kc][2], ql[kc][3], kh0, kh1);
                MMA16816(s[jj*2+1], qh[kc][0], qh[kc][1], qh[kc][2], qh[kc][3], kh2, kh3);
                MMA16816(s[jj*2+1], qh[kc][0], qh[kc][1], qh[kc][2], qh[kc][3], kl2, kl3);
                MMA16816(s[jj*2+1], ql[kc][0], ql[kc][1], ql[kc][2], ql[kc][3], kh2, kh3);
            }
        }

        #pragma unroll
        for (int j = 0; j < 8; j++)
            #pragma unroll
            for (int c = 0; c < 4; c++) s[j][c] *= 0.125f;

        if (kt * 64 + 63 > qt * 128 + w * 16) {
            #pragma unroll
            for (int j = 0; j < 8; j++) {
                int col = kt * 64 + j * 8 + qd * 2;
                if (col     > row0g) s[j][0] = -1e30f;
                if (col + 1 > row0g) s[j][1] = -1e30f;
                if (col     > row1g) s[j][2] = -1e30f;
                if (col + 1 > row1g) s[j][3] = -1e30f;
            }
        }

        float rm0 = -1e30f, rm1 = -1e30f;
        #pragma unroll
        for (int j = 0; j < 8; j++) {
            rm0 = fmaxf(rm0, fmaxf(s[j][0], s[j][1]));
            rm1 = fmaxf(rm1, fmaxf(s[j][2], s[j][3]));
        }
        rm0 = fmaxf(rm0, __shfl_xor_sync(0xffffffffu, rm0, 1));
        rm0 = fmaxf(rm0, __shfl_xor_sync(0xffffffffu, rm0, 2));
        rm1 = fmaxf(rm1, __shfl_xor_sync(0xffffffffu, rm1, 1));
        rm1 = fmaxf(rm1, __shfl_xor_sync(0xffffffffu, rm1, 2));
        float mn0 = fmaxf(mi0, rm0), mn1 = fmaxf(mi1, rm1);
        float al0 = __expf(mi0 - mn0), al1 = __expf(mi1 - mn1);
        mi0 = mn0; mi1 = mn1;
        float rs0 = 0.0f, rs1 = 0.0f;
        #pragma unroll
        for (int j = 0; j < 8; j++) {
            s[j][0] = __expf(s[j][0] - mn0);
            s[j][1] = __expf(s[j][1] - mn0);
            s[j][2] = __expf(s[j][2] - mn1);
            s[j][3] = __expf(s[j][3] - mn1);
            rs0 += s[j][0] + s[j][1];
            rs1 += s[j][2] + s[j][3];
        }
        rs0 += __shfl_xor_sync(0xffffffffu, rs0, 1);
        rs0 += __shfl_xor_sync(0xffffffffu, rs0, 2);
        rs1 += __shfl_xor_sync(0xffffffffu, rs1, 1);
        rs1 += __shfl_xor_sync(0xffffffffu, rs1, 2);
        li0 = li0 * al0 + rs0;
        li1 = li1 * al1 + rs1;

        #pragma unroll
        for (int j = 0; j < 8; j++) {
            o[j][0] *= al0; o[j][1] *= al0;
            o[j][2] *= al1; o[j][3] *= al1;
        }

        uint32_t pa[4][4];
        #pragma unroll
        for (int kc = 0; kc < 4; kc++) {
            pa[kc][0] = pack_bf2(s[2*kc  ][0], s[2*kc  ][1]);
            pa[kc][1] = pack_bf2(s[2*kc  ][2], s[2*kc  ][3]);
            pa[kc][2] = pack_bf2(s[2*kc+1][0], s[2*kc+1][1]);
            pa[kc][3] = pack_bf2(s[2*kc+1][2], s[2*kc+1][3]);
        }

        #pragma unroll
        for (int kc = 0; kc < 4; kc++) {
            #pragma unroll
            for (int jj = 0; jj < 4; jj++) {
                uint32_t addr_h = smem_u32(&Vh[(kc * 16 + (lane & 7) + ((lane >> 3) & 1) * 8) * FPITCH
                                               + (jj * 2 + (lane >> 4)) * 8]);
                uint32_t addr_l = smem_u32(&Vl[(kc * 16 + (lane & 7) + ((lane >> 3) & 1) * 8) * FPITCH
                                               + (jj * 2 + (lane >> 4)) * 8]);
                uint32_t vh0, vh1, vh2, vh3, vl0, vl1, vl2, vl3;
                LDSM_X4_T(vh0, vh1, vh2, vh3, addr_h);
                LDSM_X4_T(vl0, vl1, vl2, vl3, addr_l);
                MMA16816(o[jj*2  ], pa[kc][0], pa[kc][1], pa[kc][2], pa[kc][3], vh0, vh1);
                MMA16816(o[jj*2  ], pa[kc][0], pa[kc][1], pa[kc][2], pa[kc][3], vl0, vl1);
                MMA16816(o[jj*2+1], pa[kc][0], pa[kc][1], pa[kc][2], pa[kc][3], vh2, vh3);
                MMA16816(o[jj*2+1], pa[kc][0], pa[kc][1], pa[kc][2], pa[kc][3], vl2, vl3);
            }
        }
    }

    float inv0 = 1.0f / li0, inv1 = 1.0f / li1;
    float* zb = z + ((size_t)bb * SQ + (size_t)qt * FBM + w * 16) * DM + hh * DH;
    #pragma unroll
    for (int j = 0; j < 8; j++) {
        int col = j * 8 + qd * 2;
        *(float2*)(zb + (size_t)gid * DM + col)       = make_float2(o[j][0] * inv0, o[j][1] * inv0);
        *(float2*)(zb + (size_t)(gid + 8) * DM + col) = make_float2(o[j][2] * inv1, o[j][3] * inv1);
    }
}

// ---------------- host launcher ---------------------------------------------
static float* sym_addr(const void* symbol) {
    void* p = nullptr;
    cudaGetSymbolAddress(&p, symbol);
    return (float*)p;
}

extern "C" void kernel_launch(void* const* d_in, const int* in_sizes, int n_in,
                              void* d_out, int out_size) {
    const float* resid_pre = (const float*)d_in[0];
    const float* ln1_w = (const float*)d_in[1];
    const float* ln1_b = (const float*)d_in[2];
    const float* W_Q   = (const float*)d_in[3];
    const float* b_Q   = (const float*)d_in[4];
    const float* W_K   = (const float*)d_in[5];
    const float* b_K   = (const float*)d_in[6];
    const float* W_V   = (const float*)d_in[7];
    const float* b_V   = (const float*)d_in[8];
    const float* W_O   = (const float*)d_in[9];
    const float* b_O   = (const float*)d_in[10];
    const float* ln2_w = (const float*)d_in[11];
    const float* ln2_b = (const float*)d_in[12];
    const float* W_in  = (const float*)d_in[13];
    const float* b_in  = (const float*)d_in[14];
    const float* W_out = (const float*)d_in[15];
    const float* b_out = (const float*)d_in[16];
    float* out = (float*)d_out;

    float* xln  = sym_addr(g_xln);
    float* qb   = sym_addr(g_q);
    float* kb   = sym_addr(g_k);
    float* vb   = sym_addr(g_v);
    float* zb   = sym_addr(g_z);
    float* rmid = sym_addr(g_rmid);
    float* h2   = sym_addr(g_h2);
    float* act  = sym_addr(g_act);
    float* wq   = sym_addr(g_wq);
    float* wk   = sym_addr(g_wk);
    float* wv   = sym_addr(g_wv);

    // 1. repack QKV weights
    repack_kernel<<<(DM * DM) / 256, 256>>>(W_Q, W_K, W_V);

    // 2. LN1
    ln_kernel<<<NTOK, 256>>>(resid_pre, ln1_w, ln1_b, xln);

    // 3. QKV projections (fp16 2-pass, scatter epilogue into [b,h,s,dh])
    dim3 gq(DM / 128, NTOK / 128);
    hgemm_kernel<1><<<gq, 256>>>(xln, wq, b_Q, nullptr, qb, NTOK, DM, DM);
    hgemm_kernel<1><<<gq, 256>>>(xln, wk, b_K, nullptr, kb, NTOK, DM, DM);
    hgemm_kernel<1><<<gq, 256>>>(xln, wv, b_V, nullptr, vb, NTOK, DM, DM);

    // 4. tensor-core flash attention
    const size_t fl_smem = (size_t)(2*FBM + 4*FBN) * FPITCH * sizeof(bf16); // 73728
    cudaFuncSetAttribute(flashmma_kernel,
                         cudaFuncAttributeMaxDynamicSharedMemorySize, (int)fl_smem);
    flashmma_kernel<<<dim3(SQ / FBM, BT * NH), 256, fl_smem>>>(qb, kb, vb, zb);

    // 5. O-proj + residual -> resid_mid
    hgemm_kernel<2><<<gq, 256>>>(zb, W_O, b_O, resid_pre, rmid, NTOK, DM, DM);

    // 6. LN2
    ln_kernel<<<NTOK, 256>>>(rmid, ln2_w, ln2_b, h2);

    // 7. MLP in + ReLU
    dim3 gi(DMLP / 128, NTOK / 128);
    hgemm_kernel<3><<<gi, 256>>>(h2, W_in, b_in, nullptr, act, NTOK, DMLP, DM);

    // 8. MLP out + bias + residual -> output
    hgemm_kernel<2><<<gq, 256>>>(act, W_out, b_out, rmid, out, NTOK, DM, DMLP);
}

// round 16
// speedup vs baseline: 4.6005x; 1.5712x over previous
#include <cuda_runtime.h>
#include <cuda_bf16.h>
#include <cuda_fp16.h>
#include <stdint.h>
#include <cstdint>
#include <math.h>

// Problem constants
#define SQ   2048
#define DM   1024
#define NH   16
#define DH   64
#define BT   2
#define NTOK (BT*SQ)      // 4096
#define DMLP 4096

typedef __nv_bfloat16 bf16;

// ---------------- scratch (device globals; no allocations allowed) ----------
__device__ float g_q   [NTOK*DM];      // [B,H,S,DH] fp32 (flash input)
__device__ float g_k   [NTOK*DM];
__device__ float g_v   [NTOK*DM];
__device__ float g_rmid[NTOK*DM];

__device__ __half g_xln [NTOK*DM];     // fp16 activations
__device__ __half g_z   [NTOK*DM];
__device__ __half g_h2  [NTOK*DM];
__device__ __half g_act [NTOK*DMLP];

__device__ __half g_wq  [DM*DM];       // fp16 weights; QKV repacked [d, h*64+k]
__device__ __half g_wk  [DM*DM];
__device__ __half g_wv  [DM*DM];
__device__ __half g_wo  [DM*DM];       // [k, n] natural layout
__device__ __half g_win [DM*DMLP];
__device__ __half g_wout[DMLP*DM];

// ---------------- weight repack / convert ------------------------------------
__global__ void repack_kernel(const float* __restrict__ wq,
                              const float* __restrict__ wk,
                              const float* __restrict__ wv) {
    int idx = blockIdx.x * 256 + threadIdx.x;
    int d  = idx >> 10;
    int n  = idx & 1023;
    int src = (n >> 6) * (DM * DH) + d * DH + (n & 63);
    g_wq[idx] = __float2half_rn(wq[src]);
    g_wk[idx] = __float2half_rn(wk[src]);
    g_wv[idx] = __float2half_rn(wv[src]);
}

__global__ void conv_kernel(const float* __restrict__ src, __half* __restrict__ dst) {
    int i = (blockIdx.x * 256 + threadIdx.x) * 4;
    float4 v = *(const float4*)(src + i);
    __half2 a = __floats2half2_rn(v.x, v.y);
    __half2 b = __floats2half2_rn(v.z, v.w);
    *(__half2*)(dst + i)     = a;
    *(__half2*)(dst + i + 2) = b;
}

// ---------------- layernorm -> fp16 ------------------------------------------
__global__ void ln_kernel(const float* __restrict__ x, const float* __restrict__ w,
                          const float* __restrict__ b, __half* __restrict__ y) {
    int row = blockIdx.x;
    int t = threadIdx.x;
    const float4 xv = *(const float4*)(x + (size_t)row * DM + t * 4);
    float s  = xv.x + xv.y + xv.z + xv.w;
    float ss = xv.x*xv.x + xv.y*xv.y + xv.z*xv.z + xv.w*xv.w;
    #pragma unroll
    for (int o = 16; o; o >>= 1) {
        s  += __shfl_xor_sync(0xffffffffu, s,  o);
        ss += __shfl_xor_sync(0xffffffffu, ss, o);
    }
    __shared__ float sb[8], sb2[8];
    int wid = t >> 5, lane = t & 31;
    if (lane == 0) { sb[wid] = s; sb2[wid] = ss; }
    __syncthreads();
    if (wid == 0) {
        s  = sb[lane & 7];
        ss = sb2[lane & 7];
        #pragma unroll
        for (int o = 4; o; o >>= 1) {
            s  += __shfl_xor_sync(0xffffffffu, s,  o);
            ss += __shfl_xor_sync(0xffffffffu, ss, o);
        }
        if (lane == 0) { sb[0] = s; sb2[0] = ss; }
    }
    __syncthreads();
    float mean = sb[0] * (1.0f / DM);
    float var  = sb2[0] * (1.0f / DM) - mean * mean;
    float rstd = rsqrtf(var + 1e-5f);
    float4 wv4 = *(const float4*)(w + t * 4);
    float4 bv4 = *(const float4*)(b + t * 4);
    float o0 = (xv.x - mean) * rstd * wv4.x + bv4.x;
    float o1 = (xv.y - mean) * rstd * wv4.y + bv4.y;
    float o2 = (xv.z - mean) * rstd * wv4.z + bv4.z;
    float o3 = (xv.w - mean) * rstd * wv4.w + bv4.w;
    size_t base = (size_t)row * DM + t * 4;
    *(__half2*)(y + base)     = __floats2half2_rn(o0, o1);
    *(__half2*)(y + base + 2) = __floats2half2_rn(o2, o3);
}

// ---------------- mma helpers ------------------------------------------------
__device__ __forceinline__ uint32_t smem_u32(const void* p) {
    return (uint32_t)__cvta_generic_to_shared(p);
}
__device__ __forceinline__ void cp16(uint32_t dst, const void* src) {
    asm volatile("cp.async.cg.shared.global [%0], [%1], 16;"
                 :: "r"(dst), "l"((unsigned long long)__cvta_generic_to_global(src)));
}
#define CP_COMMIT() asm volatile("cp.async.commit_group;")
#define CP_WAIT1()  asm volatile("cp.async.wait_group 1;")
#define CP_WAIT0()  asm volatile("cp.async.wait_group 0;")

#define LDSM_X4(r0,r1,r2,r3,addr) \
    asm volatile("ldmatrix.sync.aligned.m8n8.x4.shared.b16 {%0,%1,%2,%3}, [%4];" \
        : "=r"(r0),"=r"(r1),"=r"(r2),"=r"(r3) : "r"(addr))
#define LDSM_X4_T(r0,r1,r2,r3,addr) \
    asm volatile("ldmatrix.sync.aligned.m8n8.x4.trans.shared.b16 {%0,%1,%2,%3}, [%4];" \
        : "=r"(r0),"=r"(r1),"=r"(r2),"=r"(r3) : "r"(addr))

// bf16 mma (flash attention)
#define MMA16816(c, a0,a1,a2,a3, b0,b1) \
    asm volatile("mma.sync.aligned.m16n8k16.row.col.f32.bf16.bf16.f32 " \
        "{%0,%1,%2,%3}, {%4,%5,%6,%7}, {%8,%9}, {%0,%1,%2,%3};" \
        : "+f"(c[0]),"+f"(c[1]),"+f"(c[2]),"+f"(c[3]) \
        : "r"(a0),"r"(a1),"r"(a2),"r"(a3), "r"(b0),"r"(b1))

// fp16 mma (GEMMs)
#define MMA16816H(c, a0,a1,a2,a3, b0,b1) \
    asm volatile("mma.sync.aligned.m16n8k16.row.col.f32.f16.f16.f32 " \
        "{%0,%1,%2,%3}, {%4,%5,%6,%7}, {%8,%9}, {%0,%1,%2,%3};" \
        : "+f"(c[0]),"+f"(c[1]),"+f"(c[2]),"+f"(c[3]) \
        : "r"(a0),"r"(a1),"r"(a2),"r"(a3), "r"(b0),"r"(b1))

__device__ __forceinline__ uint32_t pack_bf2(float a, float b) {
    __nv_bfloat162 t = __floats2bfloat162_rn(a, b);
    return *reinterpret_cast<uint32_t*>(&t);
}
__device__ __forceinline__ void split_bf(float f, bf16& h, bf16& l) {
    h = __float2bfloat16(f);
    l = __float2bfloat16(f - __bfloat162float(h));
}

// ---------------- fp16 single-pass GEMM, cp.async 2-stage --------------------
// C = A*B (+bias/epilogue). A fp16 [M,K]; B fp16 [K,N] (both pre-converted).
// CTA tile 128x128x32, 8 warps (2x4), warp tile 64x32, 16 MMA/warp/tile.
// MODE 1: scatter [b,h,s,dh] fp32 + bias; MODE 2: +bias+R fp32; MODE 3: relu -> fp16.
#define APAD 40
#define BPAD 136
#define A_BYTES (128*APAD*2)          // 10240
#define B_BYTES (32*BPAD*2)           // 8704
#define STAGE_B (A_BYTES + B_BYTES)   // 18944
#define HGEMM_SMEM (2*STAGE_B)        // 37888 (< 48K, no attribute needed)

template <int MODE>
__global__ __launch_bounds__(256, 2)
void hgemm_kernel(const __half* __restrict__ A, const __half* __restrict__ B,
                  const float* __restrict__ bias, const float* __restrict__ R,
                  float* __restrict__ C, __half* __restrict__ Ch,
                  int M, int N, int K) {
    extern __shared__ __align__(16) char hs[];
    uint32_t s_base = smem_u32(hs);

    int tid = threadIdx.x;
    int lane = tid & 31;
    int warp = tid >> 5;
    int wm = warp >> 2;        // 0..1
    int wn = warp & 3;         // 0..3
    int m0 = blockIdx.y * 128, n0 = blockIdx.x * 128;

    float acc[4][4][4];
    #pragma unroll
    for (int i = 0; i < 4; i++)
        #pragma unroll
        for (int j = 0; j < 4; j++)
            #pragma unroll
            for (int c = 0; c < 4; c++) acc[i][j][c] = 0.0f;

    // fragment smem base addresses (stage 0)
    uint32_t a_frag0 = s_base + (uint32_t)(((wm*64 + (lane & 15)) * APAD + (lane >> 4) * 8) * 2);
    uint32_t b_frag0 = s_base + (uint32_t)A_BYTES
                     + (uint32_t)(((lane & 15) * BPAD + wn*32 + (lane >> 4) * 8) * 2);

    auto load_stage = [&](int k0, int st) {
        uint32_t sb = s_base + (uint32_t)st * STAGE_B;
        #pragma unroll
        for (int h = 0; h < 2; h++) {
            int idx = tid + h * 256;
            // A: 128 rows x 4 chunks of 8 halfs
            int r  = idx >> 2,  c8  = (idx & 3)  * 8;
            cp16(sb + (uint32_t)((r * APAD + c8) * 2),
                 A + (size_t)(m0 + r) * K + k0 + c8);
            // B: 32 rows x 16 chunks
            int rb = idx >> 4, cb8 = (idx & 15) * 8;
            cp16(sb + (uint32_t)A_BYTES + (uint32_t)((rb * BPAD + cb8) * 2),
                 B + (size_t)(k0 + rb) * N + n0 + cb8);
        }
    };

    int nk = K >> 5;
    load_stage(0, 0);
    CP_COMMIT();

    for (int kt = 0; kt < nk; kt++) {
        int st = kt & 1;
        if (kt + 1 < nk) {
            load_stage((kt + 1) << 5, st ^ 1);
            CP_COMMIT();
            CP_WAIT1();
        } else {
            CP_WAIT0();
        }
        __syncthreads();

        uint32_t so = (uint32_t)(st * STAGE_B);
        #pragma unroll
        for (int ks = 0; ks < 2; ks++) {
            uint32_t bh[8];
            {
                uint32_t off = so + (uint32_t)(ks * 16 * BPAD * 2);
                LDSM_X4_T(bh[0], bh[1], bh[2], bh[3], b_frag0 + off);
                LDSM_X4_T(bh[4], bh[5], bh[6], bh[7], b_frag0 + off + 16 * 2);
            }
            #pragma unroll
            for (int i = 0; i < 4; i++) {
                uint32_t a0, a1, a2, a3;
                uint32_t aoff = so + (uint32_t)((i * 16 * APAD + ks * 16) * 2);
                LDSM_X4(a0, a1, a2, a3, a_frag0 + aoff);
                #pragma unroll
                for (int j = 0; j < 4; j++)
                    MMA16816H(acc[i][j], a0, a1, a2, a3, bh[2*j], bh[2*j+1]);
            }
        }
        __syncthreads();
    }

    // ---- epilogue ----
    int gid = lane >> 2;
    int tid4 = lane & 3;
    #pragma unroll
    for (int i = 0; i < 4; i++) {
        #pragma unroll
        for (int j = 0; j < 4; j++) {
            #pragma unroll
            for (int cp = 0; cp < 2; cp++) {         // c pairs (0,1) and (2,3)
                int m = m0 + wm * 64 + i * 16 + gid + cp * 8;
                int n = n0 + wn * 32 + j * 8 + tid4 * 2;
                float v0 = acc[i][j][cp*2 + 0] + bias[n];
                float v1 = acc[i][j][cp*2 + 1] + bias[n + 1];
                if (MODE == 1) {
                    int bb = m >> 11;
                    int sq = m & (SQ - 1);
                    int h  = n >> 6;
                    int dk = n & 63;
                    *(float2*)(C + (((size_t)(bb * NH + h)) * SQ + sq) * DH + dk)
                        = make_float2(v0, v1);
                } else if (MODE == 2) {
                    const float2 r2 = *(const float2*)(R + (size_t)m * N + n);
                    *(float2*)(C + (size_t)m * N + n) = make_float2(v0 + r2.x, v1 + r2.y);
                } else {
                    *(__half2*)(Ch + (size_t)m * N + n)
                        = __floats2half2_rn(fmaxf(v0, 0.0f), fmaxf(v1, 0.0f));
                }
            }
        }
    }
}

// ---------------- tensor-core flash attention (bf16 3-pass) ------------------
// z out now fp16.
#define FBM 128
#define FBN 64
#define FPITCH 72

__global__ __launch_bounds__(256, 1)
void flashmma_kernel(const float* __restrict__ q, const float* __restrict__ k,
                     const float* __restrict__ v, __half* __restrict__ z) {
    extern __shared__ bf16 fsm[];
    bf16* Qh = fsm;
    bf16* Ql = Qh + FBM * FPITCH;
    bf16* Kh = Ql + FBM * FPITCH;
    bf16* Kl = Kh + FBN * FPITCH;
    bf16* Vh = Kl + FBN * FPITCH;
    bf16* Vl = Vh + FBN * FPITCH;

    int qt = blockIdx.x, bh = blockIdx.y;
    int bb = bh >> 4, hh = bh & 15;
    int tid = threadIdx.x, lane = tid & 31, w = tid >> 5;
    int gid = lane >> 2, qd = lane & 3;

    const float* qbase = q + ((size_t)bh * SQ + (size_t)qt * FBM) * DH;
    const float* kbase = k + (size_t)bh * SQ * DH;
    const float* vbase = v + (size_t)bh * SQ * DH;

    #pragma unroll
    for (int j = 0; j < 8; j++) {
        int idx = tid + j * 256;
        int r = idx >> 4, c = (idx & 15) * 4;
        float4 t4 = *(const float4*)(qbase + (size_t)r * DH + c);
        float f[4] = {t4.x, t4.y, t4.z, t4.w};
        #pragma unroll
        for (int e = 0; e < 4; e++)
            split_bf(f[e], Qh[r * FPITCH + c + e], Ql[r * FPITCH + c + e]);
    }
    __syncthreads();

    uint32_t qh[4][4], ql[4][4];
    #pragma unroll
    for (int kc = 0; kc < 4; kc++) {
        uint32_t a1 = smem_u32(&Qh[(w * 16 + (lane & 15)) * FPITCH + kc * 16 + (lane >> 4) * 8]);
        LDSM_X4(qh[kc][0], qh[kc][1], qh[kc][2], qh[kc][3], a1);
        uint32_t a2 = smem_u32(&Ql[(w * 16 + (lane & 15)) * FPITCH + kc * 16 + (lane >> 4) * 8]);
        LDSM_X4(ql[kc][0], ql[kc][1], ql[kc][2], ql[kc][3], a2);
    }

    float o[8][4];
    #pragma unroll
    for (int j = 0; j < 8; j++)
        #pragma unroll
        for (int c = 0; c < 4; c++) o[j][c] = 0.0f;
    float mi0 = -1e30f, mi1 = -1e30f, li0 = 0.0f, li1 = 0.0f;

    int row0g = qt * FBM + w * 16 + gid;
    int row1g = row0g + 8;

    int nkt = 2 * qt + 2;
    for (int kt = 0; kt < nkt; kt++) {
        __syncthreads();
        #pragma unroll
        for (int j = 0; j < 4; j++) {
            int idx = tid + j * 256;
            int r = idx >> 4, c = (idx & 15) * 4;
            float4 t4 = *(const float4*)(kbase + ((size_t)kt * FBN + r) * DH + c);
            float f[4] = {t4.x, t4.y, t4.z, t4.w};
            #pragma unroll
            for (int e = 0; e < 4; e++)
                split_bf(f[e], Kh[r * FPITCH + c + e], Kl[r * FPITCH + c + e]);
            float4 u4 = *(const float4*)(vbase + ((size_t)kt * FBN + r) * DH + c);
            float g[4] = {u4.x, u4.y, u4.z, u4.w};
            #pragma unroll
            for (int e = 0; e < 4; e++)
                split_bf(g[e], Vh[r * FPITCH + c + e], Vl[r * FPITCH + c + e]);
        }
        __syncthreads();

        float s[8][4];
        #pragma unroll
        for (int j = 0; j < 8; j++)
            #pragma unroll
            for (int c = 0; c < 4; c++) s[j][c] = 0.0f;

        #pragma unroll
        for (int kc = 0; kc < 4; kc++) {
            #pragma unroll
            for (int jj = 0; jj < 4; jj++) {
                uint32_t addr_h = smem_u32(&Kh[((jj * 2 + (lane >> 4)) * 8 + (lane & 7)) * FPITCH
                                               + kc * 16 + ((lane >> 3) & 1) * 8]);
                uint32_t addr_l = smem_u32(&Kl[((jj * 2 + (lane >> 4)) * 8 + (lane & 7)) * FPITCH
                                               + kc * 16 + ((lane >> 3) & 1) * 8]);
                uint32_t kh0, kh1, kh2, kh3, kl0, kl1, kl2, kl3;
                LDSM_X4(kh0, kh1, kh2, kh3, addr_h);
                LDSM_X4(kl0, kl1, kl2, kl3, addr_l);
                MMA16816(s[jj*2  ], qh[kc][0], qh[kc][1], qh[kc][2], qh[kc][3], kh0, kh1);
                MMA16816(s[jj*2  ], qh[kc][0], qh[kc][1], qh[kc][2], qh[kc][3], kl0, kl1);
                MMA16816(s[jj*2  ], ql[kc][0], ql[kc][1], ql[kc][2], ql[kc][3], kh0, kh1);
                MMA16816(s[jj*2+1], qh[kc][0], qh[kc][1], qh[kc][2], qh[kc][3], kh2, kh3);
                MMA16816(s[jj*2+1], qh[kc][0], qh[kc][1], qh[kc][2], qh[kc][3], kl2, kl3);
                MMA16816(s[jj*2+1], ql[kc][0], ql[kc][1], ql[kc][2], ql[kc][3], kh2, kh3);
            }
        }

        #pragma unroll
        for (int j = 0; j < 8; j++)
            #pragma unroll
            for (int c = 0; c < 4; c++) s[j][c] *= 0.125f;

        if (kt * 64 + 63 > qt * 128 + w * 16) {
            #pragma unroll
            for (int j = 0; j < 8; j++) {
                int col = kt * 64 + j * 8 + qd * 2;
                if (col     > row0g) s[j][0] = -1e30f;
                if (col + 1 > row0g) s[j][1] = -1e30f;
                if (col     > row1g) s[j][2] = -1e30f;
                if (col + 1 > row1g) s[j][3] = -1e30f;
            }
        }

        float rm0 = -1e30f, rm1 = -1e30f;
        #pragma unroll
        for (int j = 0; j < 8; j++) {
            rm0 = fmaxf(rm0, fmaxf(s[j][0], s[j][1]));
            rm1 = fmaxf(rm1, fmaxf(s[j][2], s[j][3]));
        }
        rm0 = fmaxf(rm0, __shfl_xor_sync(0xffffffffu, rm0, 1));
        rm0 = fmaxf(rm0, __shfl_xor_sync(0xffffffffu, rm0, 2));
        rm1 = fmaxf(rm1, __shfl_xor_sync(0xffffffffu, rm1, 1));
        rm1 = fmaxf(rm1, __shfl_xor_sync(0xffffffffu, rm1, 2));
        float mn0 = fmaxf(mi0, rm0), mn1 = fmaxf(mi1, rm1);
        float al0 = __expf(mi0 - mn0), al1 = __expf(mi1 - mn1);
        mi0 = mn0; mi1 = mn1;
        float rs0 = 0.0f, rs1 = 0.0f;
        #pragma unroll
        for (int j = 0; j < 8; j++) {
            s[j][0] = __expf(s[j][0] - mn0);
            s[j][1] = __expf(s[j][1] - mn0);
            s[j][2] = __expf(s[j][2] - mn1);
            s[j][3] = __expf(s[j][3] - mn1);
            rs0 += s[j][0] + s[j][1];
            rs1 += s[j][2] + s[j][3];
        }
        rs0 += __shfl_xor_sync(0xffffffffu, rs0, 1);
        rs0 += __shfl_xor_sync(0xffffffffu, rs0, 2);
        rs1 += __shfl_xor_sync(0xffffffffu, rs1, 1);
        rs1 += __shfl_xor_sync(0xffffffffu, rs1, 2);
        li0 = li0 * al0 + rs0;
        li1 = li1 * al1 + rs1;

        #pragma unroll
        for (int j = 0; j < 8; j++) {
            o[j][0] *= al0; o[j][1] *= al0;
            o[j][2] *= al1; o[j][3] *= al1;
        }

        uint32_t pa[4][4];
        #pragma unroll
        for (int kc = 0; kc < 4; kc++) {
            pa[kc][0] = pack_bf2(s[2*kc  ][0], s[2*kc  ][1]);
            pa[kc][1] = pack_bf2(s[2*kc  ][2], s[2*kc  ][3]);
            pa[kc][2] = pack_bf2(s[2*kc+1][0], s[2*kc+1][1]);
            pa[kc][3] = pack_bf2(s[2*kc+1][2], s[2*kc+1][3]);
        }

        #pragma unroll
        for (int kc = 0; kc < 4; kc++) {
            #pragma unroll
            for (int jj = 0; jj < 4; jj++) {
                uint32_t addr_h = smem_u32(&Vh[(kc * 16 + (lane & 7) + ((lane >> 3) & 1) * 8) * FPITCH
                                               + (jj * 2 + (lane >> 4)) * 8]);
                uint32_t addr_l = smem_u32(&Vl[(kc * 16 + (lane & 7) + ((lane >> 3) & 1) * 8) * FPITCH
                                               + (jj * 2 + (lane >> 4)) * 8]);
                uint32_t vh0, vh1, vh2, vh3, vl0, vl1, vl2, vl3;
                LDSM_X4_T(vh0, vh1, vh2, vh3, addr_h);
                LDSM_X4_T(vl0, vl1, vl2, vl3, addr_l);
                MMA16816(o[jj*2  ], pa[kc][0], pa[kc][1], pa[kc][2], pa[kc][3], vh0, vh1);
                MMA16816(o[jj*2  ], pa[kc][0], pa[kc][1], pa[kc][2], pa[kc][3], vl0, vl1);
                MMA16816(o[jj*2+1], pa[kc][0], pa[kc][1], pa[kc][2], pa[kc][3], vh2, vh3);
                MMA16816(o[jj*2+1], pa[kc][0], pa[kc][1], pa[kc][2], pa[kc][3], vl2, vl3);
            }
        }
    }

    float inv0 = 1.0f / li0, inv1 = 1.0f / li1;
    __half* zb = z + ((size_t)bb * SQ + (size_t)qt * FBM + w * 16) * DM + hh * DH;
    #pragma unroll
    for (int j = 0; j < 8; j++) {
        int col = j * 8 + qd * 2;
        *(__half2*)(zb + (size_t)gid * DM + col)
            = __floats2half2_rn(o[j][0] * inv0, o[j][1] * inv0);
        *(__half2*)(zb + (size_t)(gid + 8) * DM + col)
            = __floats2half2_rn(o[j][2] * inv1, o[j][3] * inv1);
    }
}

// ---------------- host launcher ---------------------------------------------
template <typename T>
static T* sym_addr(const void* symbol) {
    void* p = nullptr;
    cudaGetSymbolAddress(&p, symbol);
    return (T*)p;
}

extern "C" void kernel_launch(void* const* d_in, const int* in_sizes, int n_in,
                              void* d_out, int out_size) {
    const float* resid_pre = (const float*)d_in[0];
    const float* ln1_w = (const float*)d_in[1];
    const float* ln1_b = (const float*)d_in[2];
    const float* W_Q   = (const float*)d_in[3];
    const float* b_Q   = (const float*)d_in[4];
    const float* W_K   = (const float*)d_in[5];
    const float* b_K   = (const float*)d_in[6];
    const float* W_V   = (const float*)d_in[7];
    const float* b_V   = (const float*)d_in[8];
    const float* W_O   = (const float*)d_in[9];
    const float* b_O   = (const float*)d_in[10];
    const float* ln2_w = (const float*)d_in[11];
    const float* ln2_b = (const float*)d_in[12];
    const float* W_in  = (const float*)d_in[13];
    const float* b_in  = (const float*)d_in[14];
    const float* W_out = (const float*)d_in[15];
    const float* b_out = (const float*)d_in[16];
    float* out = (float*)d_out;

    float* qb   = sym_addr<float>(g_q);
    float* kb   = sym_addr<float>(g_k);
    float* vb   = sym_addr<float>(g_v);
    float* rmid = sym_addr<float>(g_rmid);

    __half* xln = sym_addr<__half>(g_xln);
    __half* zb  = sym_addr<__half>(g_z);
    __half* h2  = sym_addr<__half>(g_h2);
    __half* act = sym_addr<__half>(g_act);
    __half* wq  = sym_addr<__half>(g_wq);
    __half* wk  = sym_addr<__half>(g_wk);
    __half* wv  = sym_addr<__half>(g_wv);
    __half* wo  = sym_addr<__half>(g_wo);
    __half* win = sym_addr<__half>(g_win);
    __half* wout= sym_addr<__half>(g_wout);

    // 1. weight prep: QKV repack->fp16; others straight fp16 convert
    repack_kernel<<<(DM * DM) / 256, 256>>>(W_Q, W_K, W_V);
    conv_kernel<<<(DM * DM) / 1024, 256>>>(W_O, wo);
    conv_kernel<<<(DM * DMLP) / 1024, 256>>>(W_in, win);
    conv_kernel<<<(DMLP * DM) / 1024, 256>>>(W_out, wout);

    // 2. LN1 -> fp16
    ln_kernel<<<NTOK, 256>>>(resid_pre, ln1_w, ln1_b, xln);

    // 3. QKV projections (fp16 single-pass, scatter to [b,h,s,dh] fp32)
    dim3 gq(DM / 128, NTOK / 128);
    hgemm_kernel<1><<<gq, 256, HGEMM_SMEM>>>(xln, wq, b_Q, nullptr, qb, nullptr, NTOK, DM, DM);
    hgemm_kernel<1><<<gq, 256, HGEMM_SMEM>>>(xln, wk, b_K, nullptr, kb, nullptr, NTOK, DM, DM);
    hgemm_kernel<1><<<gq, 256, HGEMM_SMEM>>>(xln, wv, b_V, nullptr, vb, nullptr, NTOK, DM, DM);

    // 4. tensor-core flash attention -> z fp16
    const size_t fl_smem = (size_t)(2*FBM + 4*FBN) * FPITCH * sizeof(bf16); // 73728
    cudaFuncSetAttribute(flashmma_kernel,
                         cudaFuncAttributeMaxDynamicSharedMemorySize, (int)fl_smem);
    flashmma_kernel<<<dim3(SQ / FBM, BT * NH), 256, fl_smem>>>(qb, kb, vb, zb);

    // 5. O-proj + residual -> resid_mid (fp32)
    hgemm_kernel<2><<<gq, 256, HGEMM_SMEM>>>(zb, wo, b_O, resid_pre, rmid, nullptr, NTOK, DM, DM);

    // 6. LN2 -> fp16
    ln_kernel<<<NTOK, 256>>>(rmid, ln2_w, ln2_b, h2);

    // 7. MLP in + ReLU -> act fp16
    dim3 gi(DMLP / 128, NTOK / 128);
    hgemm_kernel<3><<<gi, 256, HGEMM_SMEM>>>(h2, win, b_in, nullptr, nullptr, act, NTOK, DMLP, DM);

    // 8. MLP out + bias + residual -> output (fp32)
    hgemm_kernel<2><<<gq, 256, HGEMM_SMEM>>>(act, wout, b_out, rmid, out, nullptr, NTOK, DM, DMLP);
}